// round 1
// baseline (speedup 1.0000x reference)
#include <cuda_runtime.h>
#include <math.h>

// Problem constants
#define BQ   4
#define CH   256
#define HH   64
#define WW   64
#define HW   (HH*WW)          // 4096
#define VT   (BQ*HW)          // 16384 vertices
#define NP   2048             // past samples
#define NCLS 4
#define TEMP_INV 10.0f
#define EPS  1e-8f

// Scratch (allocation-free: __device__ globals)
__device__ float g_Xn[VT*CH];     // normalized X, row-major [v][d]  (16.8 MB)
__device__ float g_Pn[NP*CH];     // normalized past samples [n][d]  (2 MB)
__device__ float g_invn[VT];
__device__ int   g_clsV[VT];
__device__ int   g_clsP[NP];
__device__ float g_same[VT];
__device__ float g_other[VT];
__device__ int   g_cnt[NCLS];

// ---------------------------------------------------------------------------
// Kernel 1: per-vertex inverse norm of X, vertex class from y, zero accum.
// X is (B, C, H, W): for vertex m=(b,hw), elements stride HW apart (coalesced
// across threads since consecutive m -> consecutive hw).
// ---------------------------------------------------------------------------
__global__ void prep_x_norm(const float* __restrict__ X,
                            const float* __restrict__ Y) {
    int m = blockIdx.x * blockDim.x + threadIdx.x;
    if (m >= VT) return;
    int b  = m >> 12;          // /4096
    int hw = m & (HW - 1);
    const float* xb = X + (size_t)b * CH * HW + hw;
    float acc = 0.0f;
#pragma unroll 8
    for (int d = 0; d < CH; d++) {
        float v = xb[(size_t)d * HW];
        acc = fmaf(v, v, acc);
    }
    g_invn[m] = 1.0f / fmaxf(sqrtf(acc), EPS);

    const float* yb = Y + (size_t)b * NCLS * HW + hw;
    float best = yb[0]; int bc = 0;
#pragma unroll
    for (int k = 1; k < NCLS; k++) {
        float v = yb[(size_t)k * HW];
        if (v > best) { best = v; bc = k; }
    }
    g_clsV[m]  = bc;
    g_same[m]  = 0.0f;
    g_other[m] = 0.0f;
    if (m < NCLS) g_cnt[m] = 0;
}

// ---------------------------------------------------------------------------
// Kernel 2: normalize past samples (warp per sample), sample class + counts.
// ---------------------------------------------------------------------------
__global__ void prep_p(const float* __restrict__ P,
                       const float* __restrict__ L) {
    int gwarp = (blockIdx.x * blockDim.x + threadIdx.x) >> 5;
    int lane  = threadIdx.x & 31;
    if (gwarp >= NP) return;
    const float* p = P + (size_t)gwarp * CH;
    float v[8];
    float acc = 0.0f;
#pragma unroll
    for (int j = 0; j < 8; j++) {
        v[j] = p[lane + j * 32];
        acc = fmaf(v[j], v[j], acc);
    }
#pragma unroll
    for (int o = 16; o; o >>= 1) acc += __shfl_xor_sync(0xffffffffu, acc, o);
    float inv = 1.0f / fmaxf(sqrtf(acc), EPS);
    float* out = g_Pn + (size_t)gwarp * CH;
#pragma unroll
    for (int j = 0; j < 8; j++) out[lane + j * 32] = v[j] * inv;
    if (lane == 0) {
        const float* l = L + gwarp * NCLS;
        float best = l[0]; int bc = 0;
#pragma unroll
        for (int k = 1; k < NCLS; k++) if (l[k] > best) { best = l[k]; bc = k; }
        g_clsP[gwarp] = bc;
        atomicAdd(&g_cnt[bc], 1);
    }
}

// ---------------------------------------------------------------------------
// Kernel 3: transpose X (C-major -> vertex-major) with normalization fused.
// Classic 32x32 shared tile, coalesced loads and stores.
// ---------------------------------------------------------------------------
__global__ void transpose_x(const float* __restrict__ X) {
    __shared__ float s[32][33];
    int b  = blockIdx.z;
    int v0 = blockIdx.x * 32;
    int d0 = blockIdx.y * 32;
    int tx = threadIdx.x, ty = threadIdx.y;   // 32 x 8
    const float* xb = X + (size_t)b * CH * HW;
#pragma unroll
    for (int j = 0; j < 32; j += 8)
        s[ty + j][tx] = xb[(size_t)(d0 + ty + j) * HW + v0 + tx];
    __syncthreads();
#pragma unroll
    for (int j = 0; j < 32; j += 8) {
        int m = b * HW + v0 + ty + j;
        g_Xn[(size_t)m * CH + d0 + tx] = s[tx][ty + j] * g_invn[m];
    }
}

// ---------------------------------------------------------------------------
// Kernel 4: fused GEMM + exp + per-row same/other class reduction.
// BM=BN=128, BK=8, 256 threads, 8x8 microtile per thread.
// Rows = vertices, cols = past samples. For each row-group of 8 rows, the 16
// threads sharing ty form one half-warp -> shuffle reduce, single REDG per row.
// ---------------------------------------------------------------------------
#define BM 128
#define BN 128
#define BK 8

__global__ __launch_bounds__(256) void gemm_exp(void) {
    __shared__ float As[BK][BM];
    __shared__ float Bs[BK][BN];
    __shared__ int   sClsA[BM];
    __shared__ int   sClsB[BN];

    int tid = threadIdx.x;
    int m0 = blockIdx.y * BM;
    int n0 = blockIdx.x * BN;

    if (tid < 128) {
        sClsA[tid] = g_clsV[m0 + tid];
        sClsB[tid] = g_clsP[n0 + tid];
    }

    int lr = tid >> 1;            // 0..127 (row within tile)
    int lk = (tid & 1) * 4;       // 0 or 4
    int tx = tid & 15;            // 16x16 thread grid
    int ty = tid >> 4;

    const float* Aptr = g_Xn + (size_t)(m0 + lr) * CH + lk;
    const float* Bptr = g_Pn + (size_t)(n0 + lr) * CH + lk;

    float acc[8][8];
#pragma unroll
    for (int i = 0; i < 8; i++)
#pragma unroll
        for (int j = 0; j < 8; j++) acc[i][j] = 0.0f;

    for (int k0 = 0; k0 < CH; k0 += BK) {
        float4 a  = *(const float4*)(Aptr + k0);
        float4 b4 = *(const float4*)(Bptr + k0);
        __syncthreads();
        As[lk + 0][lr] = a.x;  As[lk + 1][lr] = a.y;
        As[lk + 2][lr] = a.z;  As[lk + 3][lr] = a.w;
        Bs[lk + 0][lr] = b4.x; Bs[lk + 1][lr] = b4.y;
        Bs[lk + 2][lr] = b4.z; Bs[lk + 3][lr] = b4.w;
        __syncthreads();
#pragma unroll
        for (int k = 0; k < BK; k++) {
            float ra[8], rb[8];
            *(float4*)(ra)     = *(const float4*)&As[k][ty * 8];
            *(float4*)(ra + 4) = *(const float4*)&As[k][ty * 8 + 4];
            *(float4*)(rb)     = *(const float4*)&Bs[k][tx * 8];
            *(float4*)(rb + 4) = *(const float4*)&Bs[k][tx * 8 + 4];
#pragma unroll
            for (int i = 0; i < 8; i++)
#pragma unroll
                for (int j = 0; j < 8; j++)
                    acc[i][j] = fmaf(ra[i], rb[j], acc[i][j]);
        }
    }

    // exp + per-row class-bucket accumulation
#pragma unroll
    for (int i = 0; i < 8; i++) {
        int   cv = sClsA[ty * 8 + i];
        float s  = 0.0f, o = 0.0f;
#pragma unroll
        for (int j = 0; j < 8; j++) {
            float e = __expf((acc[i][j] - 1.0f) * TEMP_INV);
            if (sClsB[tx * 8 + j] == cv) s += e; else o += e;
        }
        // reduce across the 16 threads (same ty) -> one half-warp
#pragma unroll
        for (int off = 8; off; off >>= 1) {
            s += __shfl_xor_sync(0xffffffffu, s, off);
            o += __shfl_xor_sync(0xffffffffu, o, off);
        }
        if (tx == 0) {
            atomicAdd(&g_same[m0 + ty * 8 + i], s);
            atomicAdd(&g_other[m0 + ty * 8 + i], o);
        }
    }
}

// ---------------------------------------------------------------------------
// Kernel 5: ratios + mean
// ---------------------------------------------------------------------------
__global__ void finalize(float* __restrict__ out) {
    __shared__ float red[256];
    int tid = threadIdx.x;
    float acc = 0.0f;
    for (int m = tid; m < VT; m += 256) {
        int   c   = g_clsV[m];
        float cnt = (float)g_cnt[c];
        float sm  = ((float)NP - cnt) + g_same[m];
        float ot  = cnt + g_other[m];
        acc += sm / ot;
    }
    red[tid] = acc;
    __syncthreads();
    for (int s = 128; s; s >>= 1) {
        if (tid < s) red[tid] += red[tid + s];
        __syncthreads();
    }
    if (tid == 0) out[0] = red[0] / (float)VT;
}

// ---------------------------------------------------------------------------
extern "C" void kernel_launch(void* const* d_in, const int* in_sizes, int n_in,
                              void* d_out, int out_size) {
    const float* X = (const float*)d_in[0];   // (4,256,64,64)
    const float* Y = (const float*)d_in[1];   // (4,4,64,64)
    const float* P = (const float*)d_in[2];   // (2048,256)
    const float* L = (const float*)d_in[3];   // (2048,4)
    float* out = (float*)d_out;

    prep_x_norm<<<VT / 256, 256>>>(X, Y);
    prep_p<<<(NP * 32) / 256, 256>>>(P, L);
    transpose_x<<<dim3(HW / 32, CH / 32, BQ), dim3(32, 8)>>>(X);
    gemm_exp<<<dim3(NP / BN, VT / BM), 256>>>();
    finalize<<<1, 256>>>(out);
}

// round 6
// speedup vs baseline: 4.5806x; 4.5806x over previous
#include <cuda_runtime.h>
#include <cuda_bf16.h>
#include <cstdint>
#include <math.h>

// Problem constants
#define BQ   4
#define CH   256
#define HW   4096
#define VT   (BQ*HW)          // 16384 vertices
#define NP   2048             // past samples
#define NCLS 4
#define TEMP_INV 10.0f
#define EPS  1e-8f

// GEMM tiling
#define GM 128
#define GN 128

// SMEM layout: padded rows (264 bf16 = 528 B) for conflict-free ldmatrix
#define ASTRIDE   528
#define OFF_A     0
#define OFF_B     (GM*ASTRIDE)            // 67584
#define OFF_CLSA  (2*GM*ASTRIDE)          // 135168
#define OFF_CLSB  (OFF_CLSA + 512)
#define SMEM_TOTAL (OFF_CLSB + 512)       // 136192

// Scratch (allocation-free: __device__ globals)
__device__ __nv_bfloat16 g_Xbf[VT*CH];   // normalized X bf16 [v][d]
__device__ __nv_bfloat16 g_Pbf[NP*CH];   // normalized P bf16 [n][d]
__device__ float g_invn[VT];
__device__ int   g_clsV[VT];
__device__ int   g_clsP[NP];
__device__ float g_same[VT];
__device__ float g_other[VT];
__device__ int   g_cnt[NCLS];
__device__ float g_sum;

__device__ __forceinline__ uint32_t smem_u32(const void* p) {
    uint32_t a;
    asm("{ .reg .u64 t; cvta.to.shared.u64 t, %1; cvt.u32.u64 %0, t; }" : "=r"(a) : "l"(p));
    return a;
}

__device__ __forceinline__ void ldsm_x4(uint32_t addr, uint32_t& r0, uint32_t& r1,
                                        uint32_t& r2, uint32_t& r3) {
    asm volatile("ldmatrix.sync.aligned.m8n8.x4.shared.b16 {%0,%1,%2,%3}, [%4];"
                 : "=r"(r0), "=r"(r1), "=r"(r2), "=r"(r3) : "r"(addr));
}

__device__ __forceinline__ void mma_bf16(float* c, const uint32_t* a, const uint32_t* b) {
    asm volatile(
        "mma.sync.aligned.m16n8k16.row.col.f32.bf16.bf16.f32 "
        "{%0,%1,%2,%3}, {%4,%5,%6,%7}, {%8,%9}, {%0,%1,%2,%3};"
        : "+f"(c[0]), "+f"(c[1]), "+f"(c[2]), "+f"(c[3])
        : "r"(a[0]), "r"(a[1]), "r"(a[2]), "r"(a[3]), "r"(b[0]), "r"(b[1]));
}

// ---------------------------------------------------------------------------
// Kernel 1: per-vertex inverse norm, vertex class, zero accumulators
// ---------------------------------------------------------------------------
__global__ void prep_x_norm(const float* __restrict__ X,
                            const float* __restrict__ Y) {
    int m = blockIdx.x * blockDim.x + threadIdx.x;
    if (m >= VT) return;
    int b  = m >> 12;
    int hw = m & (HW - 1);
    const float* xb = X + (size_t)b * CH * HW + hw;
    float acc = 0.0f;
#pragma unroll 8
    for (int d = 0; d < CH; d++) {
        float v = xb[(size_t)d * HW];
        acc = fmaf(v, v, acc);
    }
    g_invn[m] = 1.0f / fmaxf(sqrtf(acc), EPS);

    const float* yb = Y + (size_t)b * NCLS * HW + hw;
    float best = yb[0]; int bc = 0;
#pragma unroll
    for (int k = 1; k < NCLS; k++) {
        float v = yb[(size_t)k * HW];
        if (v > best) { best = v; bc = k; }
    }
    g_clsV[m]  = bc;
    g_same[m]  = 0.0f;
    g_other[m] = 0.0f;
    if (m < NCLS) g_cnt[m] = 0;
    if (m == 0)   g_sum = 0.0f;
}

// ---------------------------------------------------------------------------
// Kernel 2: normalize past samples -> bf16, class + counts
// ---------------------------------------------------------------------------
__global__ void prep_p(const float* __restrict__ P,
                       const float* __restrict__ L) {
    int gwarp = (blockIdx.x * blockDim.x + threadIdx.x) >> 5;
    int lane  = threadIdx.x & 31;
    if (gwarp >= NP) return;
    const float* p = P + (size_t)gwarp * CH;
    float v[8];
    float acc = 0.0f;
#pragma unroll
    for (int j = 0; j < 8; j++) {
        v[j] = p[lane + j * 32];
        acc = fmaf(v[j], v[j], acc);
    }
#pragma unroll
    for (int o = 16; o; o >>= 1) acc += __shfl_xor_sync(0xffffffffu, acc, o);
    float inv = 1.0f / fmaxf(sqrtf(acc), EPS);
    __nv_bfloat16* out = g_Pbf + (size_t)gwarp * CH;
#pragma unroll
    for (int j = 0; j < 8; j++) out[lane + j * 32] = __float2bfloat16(v[j] * inv);
    if (lane == 0) {
        const float* l = L + gwarp * NCLS;
        float best = l[0]; int bc = 0;
#pragma unroll
        for (int k = 1; k < NCLS; k++) if (l[k] > best) { best = l[k]; bc = k; }
        g_clsP[gwarp] = bc;
        atomicAdd(&g_cnt[bc], 1);
    }
}

// ---------------------------------------------------------------------------
// Kernel 3: transpose + normalize X -> bf16 vertex-major
// ---------------------------------------------------------------------------
__global__ void transpose_x(const float* __restrict__ X) {
    __shared__ float s[32][33];
    int b  = blockIdx.z;
    int v0 = blockIdx.x * 32;
    int d0 = blockIdx.y * 32;
    int tx = threadIdx.x, ty = threadIdx.y;   // 32 x 8
    const float* xb = X + (size_t)b * CH * HW;
#pragma unroll
    for (int j = 0; j < 32; j += 8)
        s[ty + j][tx] = xb[(size_t)(d0 + ty + j) * HW + v0 + tx];
    __syncthreads();
#pragma unroll
    for (int j = 0; j < 32; j += 8) {
        int m = b * HW + v0 + ty + j;
        g_Xbf[(size_t)m * CH + d0 + tx] = __float2bfloat16(s[tx][ty + j] * g_invn[m]);
    }
}

// ---------------------------------------------------------------------------
// Kernel 4: bf16 mma.sync GEMM (128x128 tile, K=256 resident) + exp epilogue
// 8 warps, each owns a 64x32 warp tile: (wid>>2) m-half, (wid&3) n-quarter.
// ---------------------------------------------------------------------------
__global__ __launch_bounds__(256) void gemm_hmma(void) {
    extern __shared__ __align__(16) char smem[];
    uint32_t sb = smem_u32(smem);
    int tid  = threadIdx.x;
    int wid  = tid >> 5;
    int lane = tid & 31;

    int n0 = blockIdx.x * GN;
    int m0 = blockIdx.y * GM;

    int* sClsA = (int*)(smem + OFF_CLSA);
    int* sClsB = (int*)(smem + OFF_CLSB);
    if (tid < GM) {
        sClsA[tid] = g_clsV[m0 + tid];
        sClsB[tid] = g_clsP[n0 + tid];
    }

    // Fill SMEM tiles: src rows are 32 uint4 (256 bf16); dst rows 33 uint4 (padded)
    const uint4* Ag = (const uint4*)(g_Xbf + (size_t)m0 * CH);
    const uint4* Bg = (const uint4*)(g_Pbf + (size_t)n0 * CH);
#pragma unroll
    for (int i = 0; i < 16; i++) {
        int idx   = tid + i * 256;        // 0..4095
        int row   = idx >> 5;
        int chunk = idx & 31;
        *(uint4*)(smem + OFF_A + (row * 33 + chunk) * 16) = Ag[idx];
        *(uint4*)(smem + OFF_B + (row * 33 + chunk) * 16) = Bg[idx];
    }
    __syncthreads();

    int wm0 = (wid >> 2) * 64;
    int wn0 = (wid & 3) * 32;

    float acc[4][4][4];
#pragma unroll
    for (int mi = 0; mi < 4; mi++)
#pragma unroll
        for (int ni = 0; ni < 4; ni++)
#pragma unroll
            for (int r = 0; r < 4; r++) acc[mi][ni][r] = 0.0f;

    // ldmatrix lane addressing: (lane&15) row, (lane>>4) 16B k-half
    uint32_t aBase = sb + OFF_A + (uint32_t)(wm0 + (lane & 15)) * ASTRIDE + (lane >> 4) * 16;
    uint32_t bBase = sb + OFF_B + (uint32_t)(wn0 + (lane & 15)) * ASTRIDE + (lane >> 4) * 16;

#pragma unroll
    for (int k0 = 0; k0 < CH; k0 += 16) {
        uint32_t a[4][4], b[4][2];
#pragma unroll
        for (int mi = 0; mi < 4; mi++)
            ldsm_x4(aBase + mi * 16 * ASTRIDE + k0 * 2,
                    a[mi][0], a[mi][1], a[mi][2], a[mi][3]);
#pragma unroll
        for (int nj = 0; nj < 2; nj++) {
            uint32_t t0, t1, t2, t3;
            ldsm_x4(bBase + nj * 16 * ASTRIDE + k0 * 2, t0, t1, t2, t3);
            b[nj * 2 + 0][0] = t0; b[nj * 2 + 0][1] = t2;   // rows n0..7:  k0-7, k8-15
            b[nj * 2 + 1][0] = t1; b[nj * 2 + 1][1] = t3;   // rows n8..15
        }
#pragma unroll
        for (int mi = 0; mi < 4; mi++)
#pragma unroll
            for (int ni = 0; ni < 4; ni++)
                mma_bf16(acc[mi][ni], a[mi], b[ni]);
    }

    // Epilogue: exp + per-row same/other bucketed sums.
    // acc regs 0,1 -> row (lane>>2), cols 2*(lane&3), +1 ; regs 2,3 -> row+8.
    int colBase = wn0 + (lane & 3) * 2;
#pragma unroll
    for (int mi = 0; mi < 4; mi++) {
        int rA = wm0 + mi * 16 + (lane >> 2);
        int rB = rA + 8;
        int cvA = sClsA[rA];
        int cvB = sClsA[rB];
        float sA = 0.0f, oA = 0.0f, sB = 0.0f, oB = 0.0f;
#pragma unroll
        for (int ni = 0; ni < 4; ni++) {
            int c0 = colBase + ni * 8;
            int cls0 = sClsB[c0], cls1 = sClsB[c0 + 1];
            float e0 = __expf((acc[mi][ni][0] - 1.0f) * TEMP_INV);
            float e1 = __expf((acc[mi][ni][1] - 1.0f) * TEMP_INV);
            float e2 = __expf((acc[mi][ni][2] - 1.0f) * TEMP_INV);
            float e3 = __expf((acc[mi][ni][3] - 1.0f) * TEMP_INV);
            if (cls0 == cvA) sA += e0; else oA += e0;
            if (cls1 == cvA) sA += e1; else oA += e1;
            if (cls0 == cvB) sB += e2; else oB += e2;
            if (cls1 == cvB) sB += e3; else oB += e3;
        }
        // reduce across the 4 threads sharing each row (lane&3 = 0..3)
#pragma unroll
        for (int off = 1; off <= 2; off <<= 1) {
            sA += __shfl_xor_sync(0xffffffffu, sA, off);
            oA += __shfl_xor_sync(0xffffffffu, oA, off);
            sB += __shfl_xor_sync(0xffffffffu, sB, off);
            oB += __shfl_xor_sync(0xffffffffu, oB, off);
        }
        if ((lane & 3) == 0) {
            atomicAdd(&g_same[m0 + rA],  sA);
            atomicAdd(&g_other[m0 + rA], oA);
            atomicAdd(&g_same[m0 + rB],  sB);
            atomicAdd(&g_other[m0 + rB], oB);
        }
    }
}

// ---------------------------------------------------------------------------
// Kernel 5/6: ratios + mean
// ---------------------------------------------------------------------------
__global__ void finalize1(void) {
    __shared__ float red[256];
    int tid = threadIdx.x;
    int m = blockIdx.x * 256 + tid;
    int   c   = g_clsV[m];
    float cnt = (float)g_cnt[c];
    float sm  = ((float)NP - cnt) + g_same[m];
    float ot  = cnt + g_other[m];
    red[tid] = sm / ot;
    __syncthreads();
    for (int s = 128; s; s >>= 1) {
        if (tid < s) red[tid] += red[tid + s];
        __syncthreads();
    }
    if (tid == 0) atomicAdd(&g_sum, red[0]);
}

__global__ void finalize2(float* __restrict__ out) {
    out[0] = g_sum / (float)VT;
}

// ---------------------------------------------------------------------------
extern "C" void kernel_launch(void* const* d_in, const int* in_sizes, int n_in,
                              void* d_out, int out_size) {
    const float* X = (const float*)d_in[0];   // (4,256,64,64)
    const float* Y = (const float*)d_in[1];   // (4,4,64,64)
    const float* P = (const float*)d_in[2];   // (2048,256)
    const float* L = (const float*)d_in[3];   // (2048,4)
    float* out = (float*)d_out;

    // Unconditional every call (no static guards). Non-stream host API,
    // deterministic, legal during graph capture.
    cudaFuncSetAttribute(gemm_hmma, cudaFuncAttributeMaxDynamicSharedMemorySize, SMEM_TOTAL);

    prep_x_norm<<<VT / 256, 256>>>(X, Y);
    prep_p<<<(NP * 32) / 256, 256>>>(P, L);
    transpose_x<<<dim3(HW / 32, CH / 32, BQ), dim3(32, 8)>>>(X);
    gemm_hmma<<<dim3(NP / GN, VT / GM), 256, SMEM_TOTAL>>>();
    finalize1<<<VT / 256, 256>>>();
    finalize2<<<1, 1>>>(out);
}

// round 7
// speedup vs baseline: 4.8763x; 1.0645x over previous
#include <cuda_runtime.h>
#include <cuda_bf16.h>
#include <cstdint>
#include <math.h>

// Problem constants
#define BQ   4
#define CH   256
#define HW   4096
#define VT   (BQ*HW)          // 16384 vertices
#define NP   2048             // past samples
#define NCLS 4
#define TEMP_INV 10.0f
#define EPS  1e-8f

// GEMM tiling: persistent-A. One CTA per 128-row M block, loops 16 N-tiles.
#define GM 128
#define GN 128
#define NT (NP/GN)            // 16 n-tiles

// SMEM: padded rows (264 bf16 = 528 B) for conflict-free ldmatrix
#define ASTRIDE  528
#define TILE_SZ  (GM*ASTRIDE)            // 67584
#define OFF_A    0
#define OFF_B0   TILE_SZ                 // two B stages
#define OFF_CLSB (3*TILE_SZ)             // 202752: all 2048 sample classes (8KB)
#define OFF_CLSA (OFF_CLSB + 8192)       // 128 ints
#define OFF_RED  (OFF_CLSA + 512)        // sSame[128], sOther[128]
#define SMEM_TOTAL (OFF_RED + 1024)      // 212480 (~207.5 KB)

// Scratch (allocation-free)
__device__ __align__(256) __nv_bfloat16 g_Xbf[VT*CH];
__device__ __align__(256) __nv_bfloat16 g_Pbf[NP*CH];
__device__ __align__(256) float g_invn[VT];
__device__ __align__(256) int   g_clsV[VT];
__device__ __align__(256) int   g_clsP[NP];
__device__ __align__(256) float g_same[VT];
__device__ __align__(256) float g_other[VT];
__device__ int   g_cnt[NCLS];

__device__ __forceinline__ uint32_t smem_u32(const void* p) {
    uint32_t a;
    asm("{ .reg .u64 t; cvta.to.shared.u64 t, %1; cvt.u32.u64 %0, t; }" : "=r"(a) : "l"(p));
    return a;
}
__device__ __forceinline__ void ldsm_x4(uint32_t addr, uint32_t& r0, uint32_t& r1,
                                        uint32_t& r2, uint32_t& r3) {
    asm volatile("ldmatrix.sync.aligned.m8n8.x4.shared.b16 {%0,%1,%2,%3}, [%4];"
                 : "=r"(r0), "=r"(r1), "=r"(r2), "=r"(r3) : "r"(addr));
}
__device__ __forceinline__ void mma_bf16(float* c, const uint32_t* a, const uint32_t* b) {
    asm volatile(
        "mma.sync.aligned.m16n8k16.row.col.f32.bf16.bf16.f32 "
        "{%0,%1,%2,%3}, {%4,%5,%6,%7}, {%8,%9}, {%0,%1,%2,%3};"
        : "+f"(c[0]), "+f"(c[1]), "+f"(c[2]), "+f"(c[3])
        : "r"(a[0]), "r"(a[1]), "r"(a[2]), "r"(a[3]), "r"(b[0]), "r"(b[1]));
}
#define CP16(dst, src) \
    asm volatile("cp.async.cg.shared.global [%0], [%1], 16;" :: "r"(dst), "l"(src))
#define CP_COMMIT() asm volatile("cp.async.commit_group;" ::: "memory")
#define CP_WAIT(n)  asm volatile("cp.async.wait_group %0;" :: "n"(n) : "memory")

// ---------------------------------------------------------------------------
// Kernel 1: per-vertex inverse norm, vertex class, zero class counts
// ---------------------------------------------------------------------------
__global__ void prep_x_norm(const float* __restrict__ X,
                            const float* __restrict__ Y) {
    int m = blockIdx.x * blockDim.x + threadIdx.x;
    if (m >= VT) return;
    int b  = m >> 12;
    int hw = m & (HW - 1);
    const float* xb = X + (size_t)b * CH * HW + hw;
    float acc = 0.0f;
#pragma unroll 8
    for (int d = 0; d < CH; d++) {
        float v = xb[(size_t)d * HW];
        acc = fmaf(v, v, acc);
    }
    g_invn[m] = 1.0f / fmaxf(sqrtf(acc), EPS);

    const float* yb = Y + (size_t)b * NCLS * HW + hw;
    float best = yb[0]; int bc = 0;
#pragma unroll
    for (int k = 1; k < NCLS; k++) {
        float v = yb[(size_t)k * HW];
        if (v > best) { best = v; bc = k; }
    }
    g_clsV[m] = bc;
    if (m < NCLS) g_cnt[m] = 0;
}

// ---------------------------------------------------------------------------
// Kernel 2: normalize past samples -> bf16, class + counts
// ---------------------------------------------------------------------------
__global__ void prep_p(const float* __restrict__ P,
                       const float* __restrict__ L) {
    int gwarp = (blockIdx.x * blockDim.x + threadIdx.x) >> 5;
    int lane  = threadIdx.x & 31;
    if (gwarp >= NP) return;
    const float* p = P + (size_t)gwarp * CH;
    float v[8];
    float acc = 0.0f;
#pragma unroll
    for (int j = 0; j < 8; j++) {
        v[j] = p[lane + j * 32];
        acc = fmaf(v[j], v[j], acc);
    }
#pragma unroll
    for (int o = 16; o; o >>= 1) acc += __shfl_xor_sync(0xffffffffu, acc, o);
    float inv = 1.0f / fmaxf(sqrtf(acc), EPS);
    __nv_bfloat16* out = g_Pbf + (size_t)gwarp * CH;
#pragma unroll
    for (int j = 0; j < 8; j++) out[lane + j * 32] = __float2bfloat16(v[j] * inv);
    if (lane == 0) {
        const float* l = L + gwarp * NCLS;
        float best = l[0]; int bc = 0;
#pragma unroll
        for (int k = 1; k < NCLS; k++) if (l[k] > best) { best = l[k]; bc = k; }
        g_clsP[gwarp] = bc;
        atomicAdd(&g_cnt[bc], 1);
    }
}

// ---------------------------------------------------------------------------
// Kernel 3: transpose + normalize X -> bf16 vertex-major
// ---------------------------------------------------------------------------
__global__ void transpose_x(const float* __restrict__ X) {
    __shared__ float s[32][33];
    int b  = blockIdx.z;
    int v0 = blockIdx.x * 32;
    int d0 = blockIdx.y * 32;
    int tx = threadIdx.x, ty = threadIdx.y;   // 32 x 8
    const float* xb = X + (size_t)b * CH * HW;
#pragma unroll
    for (int j = 0; j < 32; j += 8)
        s[ty + j][tx] = xb[(size_t)(d0 + ty + j) * HW + v0 + tx];
    __syncthreads();
#pragma unroll
    for (int j = 0; j < 32; j += 8) {
        int m = b * HW + v0 + ty + j;
        g_Xbf[(size_t)m * CH + d0 + tx] = __float2bfloat16(s[tx][ty + j] * g_invn[m]);
    }
}

// ---------------------------------------------------------------------------
// Kernel 4: persistent-A bf16 HMMA GEMM. grid=128, 256 threads.
// A tile resident; 16 n-tiles with 2-stage cp.async pipeline.
// Bucket sums accumulate in registers across all tiles; one smem combine.
// ---------------------------------------------------------------------------
__global__ __launch_bounds__(256) void gemm_persist(void) {
    extern __shared__ __align__(16) char smem[];
    uint32_t sb = smem_u32(smem);
    int tid  = threadIdx.x;
    int wid  = tid >> 5;
    int lane = tid & 31;
    int m0   = blockIdx.x * GM;

    // ---- prologue: cp.async A tile + class tables + B0 (group0), B1 (group1)
    const uint4* Ag = (const uint4*)(g_Xbf + (size_t)m0 * CH);
#pragma unroll
    for (int i = 0; i < 16; i++) {
        int idx = tid + i * 256;
        int row = idx >> 5, chunk = idx & 31;
        CP16(sb + OFF_A + (row * 33 + chunk) * 16, Ag + idx);
    }
#pragma unroll
    for (int i = 0; i < 2; i++)
        CP16(sb + OFF_CLSB + (tid + i * 256) * 16, ((const uint4*)g_clsP) + tid + i * 256);
    if (tid < 32)
        CP16(sb + OFF_CLSA + tid * 16, ((const uint4*)(g_clsV + m0)) + tid);
    {
        const uint4* Bg = (const uint4*)(g_Pbf);
#pragma unroll
        for (int i = 0; i < 16; i++) {
            int idx = tid + i * 256;
            int row = idx >> 5, chunk = idx & 31;
            CP16(sb + OFF_B0 + (row * 33 + chunk) * 16, Bg + idx);
        }
    }
    CP_COMMIT();
    {
        const uint4* Bg = (const uint4*)(g_Pbf + (size_t)GN * CH);
#pragma unroll
        for (int i = 0; i < 16; i++) {
            int idx = tid + i * 256;
            int row = idx >> 5, chunk = idx & 31;
            CP16(sb + OFF_B0 + TILE_SZ + (row * 33 + chunk) * 16, Bg + idx);
        }
    }
    CP_COMMIT();

    int wm0 = (wid >> 2) * 64;      // m half
    int wn0 = (wid & 3) * 32;       // n quarter (within tile)

    uint32_t aBase = sb + OFF_A + (uint32_t)(wm0 + (lane & 15)) * ASTRIDE + (lane >> 4) * 16;
    uint32_t bOff  = (uint32_t)(wn0 + (lane & 15)) * ASTRIDE + (lane >> 4) * 16;

    const int* sClsA = (const int*)(smem + OFF_CLSA);
    const int* sClsB = (const int*)(smem + OFF_CLSB);

    // persistent bucket accumulators (rows fixed per thread)
    float sAa[4], oAa[4], sBa[4], oBa[4];
#pragma unroll
    for (int mi = 0; mi < 4; mi++) { sAa[mi] = oAa[mi] = sBa[mi] = oBa[mi] = 0.0f; }

    int colBase = wn0 + (lane & 3) * 2;

    for (int t = 0; t < NT; t++) {
        if (t < NT - 1) CP_WAIT(1); else CP_WAIT(0);
        __syncthreads();

        uint32_t bBase = sb + OFF_B0 + (uint32_t)(t & 1) * TILE_SZ + bOff;

        float acc[4][4][4];
#pragma unroll
        for (int mi = 0; mi < 4; mi++)
#pragma unroll
            for (int ni = 0; ni < 4; ni++)
#pragma unroll
                for (int r = 0; r < 4; r++) acc[mi][ni][r] = 0.0f;

#pragma unroll
        for (int k0 = 0; k0 < CH; k0 += 16) {
            uint32_t a[4][4], b[4][2];
#pragma unroll
            for (int mi = 0; mi < 4; mi++)
                ldsm_x4(aBase + mi * 16 * ASTRIDE + k0 * 2,
                        a[mi][0], a[mi][1], a[mi][2], a[mi][3]);
#pragma unroll
            for (int nj = 0; nj < 2; nj++) {
                uint32_t t0, t1, t2, t3;
                ldsm_x4(bBase + nj * 16 * ASTRIDE + k0 * 2, t0, t1, t2, t3);
                b[nj * 2 + 0][0] = t0; b[nj * 2 + 0][1] = t2;
                b[nj * 2 + 1][0] = t1; b[nj * 2 + 1][1] = t3;
            }
#pragma unroll
            for (int mi = 0; mi < 4; mi++)
#pragma unroll
                for (int ni = 0; ni < 4; ni++)
                    mma_bf16(acc[mi][ni], a[mi], b[ni]);
        }

        // per-tile epilogue: exp + bucket into persistent registers
        int nGlob = t * GN;
#pragma unroll
        for (int mi = 0; mi < 4; mi++) {
            int rA = wm0 + mi * 16 + (lane >> 2);
            int cvA = sClsA[rA];
            int cvB = sClsA[rA + 8];
#pragma unroll
            for (int ni = 0; ni < 4; ni++) {
                int c0 = nGlob + colBase + ni * 8;
                int cls0 = sClsB[c0], cls1 = sClsB[c0 + 1];
                float e0 = __expf((acc[mi][ni][0] - 1.0f) * TEMP_INV);
                float e1 = __expf((acc[mi][ni][1] - 1.0f) * TEMP_INV);
                float e2 = __expf((acc[mi][ni][2] - 1.0f) * TEMP_INV);
                float e3 = __expf((acc[mi][ni][3] - 1.0f) * TEMP_INV);
                if (cls0 == cvA) sAa[mi] += e0; else oAa[mi] += e0;
                if (cls1 == cvA) sAa[mi] += e1; else oAa[mi] += e1;
                if (cls0 == cvB) sBa[mi] += e2; else oBa[mi] += e2;
                if (cls1 == cvB) sBa[mi] += e3; else oBa[mi] += e3;
            }
        }

        __syncthreads();   // protect B buffer before reissue
        if (t + 2 < NT) {
            const uint4* Bg = (const uint4*)(g_Pbf + (size_t)(t + 2) * GN * CH);
            uint32_t dst = sb + OFF_B0 + (uint32_t)(t & 1) * TILE_SZ;
#pragma unroll
            for (int i = 0; i < 16; i++) {
                int idx = tid + i * 256;
                int row = idx >> 5, chunk = idx & 31;
                CP16(dst + (row * 33 + chunk) * 16, Bg + idx);
            }
        }
        CP_COMMIT();       // uniform commit (possibly-empty group keeps counts aligned)
    }

    // ---- final combine: smem atomics (4 contributions per row), then store
    float* sS = (float*)(smem + OFF_RED);
    float* sO = sS + 128;
    if (tid < 128) { sS[tid] = 0.0f; sO[tid] = 0.0f; }
    __syncthreads();
#pragma unroll
    for (int mi = 0; mi < 4; mi++) {
        float sA = sAa[mi], oA = oAa[mi], sB = sBa[mi], oB = oBa[mi];
#pragma unroll
        for (int off = 1; off <= 2; off <<= 1) {
            sA += __shfl_xor_sync(0xffffffffu, sA, off);
            oA += __shfl_xor_sync(0xffffffffu, oA, off);
            sB += __shfl_xor_sync(0xffffffffu, sB, off);
            oB += __shfl_xor_sync(0xffffffffu, oB, off);
        }
        if ((lane & 3) == 0) {
            int rA = wm0 + mi * 16 + (lane >> 2);
            atomicAdd(&sS[rA], sA);
            atomicAdd(&sO[rA], oA);
            atomicAdd(&sS[rA + 8], sB);
            atomicAdd(&sO[rA + 8], oB);
        }
    }
    __syncthreads();
    if (tid < 128) {
        g_same[m0 + tid]  = sS[tid];
        g_other[m0 + tid] = sO[tid];
    }
}

// ---------------------------------------------------------------------------
// Kernel 5: ratios + mean (single block)
// ---------------------------------------------------------------------------
__global__ void finalize(float* __restrict__ out) {
    __shared__ float red[1024];
    int tid = threadIdx.x;
    float acc = 0.0f;
    for (int m = tid; m < VT; m += 1024) {
        int   c   = g_clsV[m];
        float cnt = (float)g_cnt[c];
        float sm  = ((float)NP - cnt) + g_same[m];
        float ot  = cnt + g_other[m];
        acc += sm / ot;
    }
    red[tid] = acc;
    __syncthreads();
    for (int s = 512; s; s >>= 1) {
        if (tid < s) red[tid] += red[tid + s];
        __syncthreads();
    }
    if (tid == 0) out[0] = red[0] / (float)VT;
}

// ---------------------------------------------------------------------------
extern "C" void kernel_launch(void* const* d_in, const int* in_sizes, int n_in,
                              void* d_out, int out_size) {
    const float* X = (const float*)d_in[0];   // (4,256,64,64)
    const float* Y = (const float*)d_in[1];   // (4,4,64,64)
    const float* P = (const float*)d_in[2];   // (2048,256)
    const float* L = (const float*)d_in[3];   // (2048,4)
    float* out = (float*)d_out;

    cudaFuncSetAttribute(gemm_persist, cudaFuncAttributeMaxDynamicSharedMemorySize, SMEM_TOTAL);

    prep_x_norm<<<VT / 256, 256>>>(X, Y);
    prep_p<<<(NP * 32) / 256, 256>>>(P, L);
    transpose_x<<<dim3(HW / 32, CH / 32, BQ), dim3(32, 8)>>>(X);
    gemm_persist<<<VT / GM, 256, SMEM_TOTAL>>>();
    finalize<<<1, 1024>>>(out);
}

// round 8
// speedup vs baseline: 5.2109x; 1.0686x over previous
#include <cuda_runtime.h>
#include <cuda_bf16.h>
#include <cstdint>
#include <math.h>

// Problem constants
#define BQ   4
#define CH   256
#define HW   4096
#define VT   (BQ*HW)          // 16384 vertices
#define NP   2048             // past samples
#define NCLS 4
#define TEMP_INV 10.0f
#define EPS  1e-8f

// GEMM tiling: persistent-A. One CTA per 128-row M block, loops 16 N-tiles.
#define GM 128
#define GN 128
#define NT (NP/GN)            // 16 n-tiles

// SMEM: padded rows (264 bf16 = 528 B) for conflict-free ldmatrix
#define ASTRIDE  528
#define TILE_SZ  (GM*ASTRIDE)            // 67584
#define OFF_A    0
#define OFF_B0   TILE_SZ                 // two B stages
#define OFF_CLSB (3*TILE_SZ)             // 202752: all 2048 sample classes (8KB)
#define OFF_CLSA (OFF_CLSB + 8192)       // 128 ints
#define OFF_RED  (OFF_CLSA + 512)        // sSame[128], sOther[128]
#define SMEM_TOTAL (OFF_RED + 1024)      // 212480 (~207.5 KB)

// Scratch (allocation-free)
__device__ __align__(256) __nv_bfloat16 g_Xbf[VT*CH];
__device__ __align__(256) __nv_bfloat16 g_Pbf[NP*CH];
__device__ __align__(256) int   g_clsV[VT];
__device__ __align__(256) int   g_clsP[NP];
__device__ __align__(256) float g_same[VT];
__device__ __align__(256) float g_other[VT];
__device__ int   g_cnt[NCLS];

__device__ __forceinline__ uint32_t smem_u32(const void* p) {
    uint32_t a;
    asm("{ .reg .u64 t; cvta.to.shared.u64 t, %1; cvt.u32.u64 %0, t; }" : "=r"(a) : "l"(p));
    return a;
}
__device__ __forceinline__ void ldsm_x4(uint32_t addr, uint32_t& r0, uint32_t& r1,
                                        uint32_t& r2, uint32_t& r3) {
    asm volatile("ldmatrix.sync.aligned.m8n8.x4.shared.b16 {%0,%1,%2,%3}, [%4];"
                 : "=r"(r0), "=r"(r1), "=r"(r2), "=r"(r3) : "r"(addr));
}
__device__ __forceinline__ void mma_bf16(float* c, const uint32_t* a, const uint32_t* b) {
    asm volatile(
        "mma.sync.aligned.m16n8k16.row.col.f32.bf16.bf16.f32 "
        "{%0,%1,%2,%3}, {%4,%5,%6,%7}, {%8,%9}, {%0,%1,%2,%3};"
        : "+f"(c[0]), "+f"(c[1]), "+f"(c[2]), "+f"(c[3])
        : "r"(a[0]), "r"(a[1]), "r"(a[2]), "r"(a[3]), "r"(b[0]), "r"(b[1]));
}
#define CP16(dst, src) \
    asm volatile("cp.async.cg.shared.global [%0], [%1], 16;" :: "r"(dst), "l"(src))
#define CP_COMMIT() asm volatile("cp.async.commit_group;" ::: "memory")
#define CP_WAIT(n)  asm volatile("cp.async.wait_group %0;" :: "n"(n) : "memory")

// ---------------------------------------------------------------------------
// Kernel 1 (fused): single pass over X -> inverse norm, class, bf16 transpose.
// Block: 32 vertices x 256 channels, 256 threads. Grid: (HW/32, BQ).
// ---------------------------------------------------------------------------
__global__ __launch_bounds__(256) void prep_x_fused(const float* __restrict__ X,
                                                    const float* __restrict__ Y) {
    __shared__ float sx[32][257];
    __shared__ float sInv[32];
    int t  = threadIdx.x;
    int b  = blockIdx.y;
    int v0 = blockIdx.x * 32;

    if (blockIdx.x == 0 && b == 0 && t < NCLS) g_cnt[t] = 0;

    const float* xb = X + (size_t)b * CH * HW + v0;
    // load 256ch x 32v, coalesced (32 lanes span vertices)
#pragma unroll
    for (int i = 0; i < 32; i++) {
        int c = i * 8 + (t >> 5);
        int v = t & 31;
        sx[v][c] = xb[(size_t)c * HW + v];
    }
    __syncthreads();

    // sum of squares: 8 threads per vertex, 32 channels each (stride-8 to
    // spread banks), shuffle-combine
    {
        int v = t >> 3, part = t & 7;
        float acc = 0.0f;
#pragma unroll
        for (int j = 0; j < 32; j++) {
            float x = sx[v][part + 8 * j];
            acc = fmaf(x, x, acc);
        }
#pragma unroll
        for (int o = 4; o; o >>= 1) acc += __shfl_xor_sync(0xffffffffu, acc, o);
        if (part == 0) {
            sInv[v] = 1.0f / fmaxf(sqrtf(acc), EPS);
            // vertex class from one-hot y
            const float* yb = Y + (size_t)b * NCLS * HW + v0 + v;
            float best = yb[0]; int bc = 0;
#pragma unroll
            for (int k = 1; k < NCLS; k++) {
                float val = yb[(size_t)k * HW];
                if (val > best) { best = val; bc = k; }
            }
            g_clsV[b * HW + v0 + v] = bc;
        }
    }
    __syncthreads();

    // write normalized bf16, vertex-major, coalesced (packed 2 per uint)
    uint32_t* out = (uint32_t*)g_Xbf + ((size_t)(b * HW + v0)) * (CH / 2);
#pragma unroll
    for (int i = 0; i < 16; i++) {
        int idx = t + i * 256;           // 0..4095
        int v = idx >> 7, cu = idx & 127;
        float inv = sInv[v];
        __nv_bfloat162 pk = __floats2bfloat162_rn(sx[v][2 * cu] * inv,
                                                  sx[v][2 * cu + 1] * inv);
        out[(size_t)v * 128 + cu] = *(uint32_t*)&pk;
    }
}

// ---------------------------------------------------------------------------
// Kernel 2: normalize past samples -> bf16, class + counts
// ---------------------------------------------------------------------------
__global__ void prep_p(const float* __restrict__ P,
                       const float* __restrict__ L) {
    int gwarp = (blockIdx.x * blockDim.x + threadIdx.x) >> 5;
    int lane  = threadIdx.x & 31;
    if (gwarp >= NP) return;
    const float* p = P + (size_t)gwarp * CH;
    float v[8];
    float acc = 0.0f;
#pragma unroll
    for (int j = 0; j < 8; j++) {
        v[j] = p[lane + j * 32];
        acc = fmaf(v[j], v[j], acc);
    }
#pragma unroll
    for (int o = 16; o; o >>= 1) acc += __shfl_xor_sync(0xffffffffu, acc, o);
    float inv = 1.0f / fmaxf(sqrtf(acc), EPS);
    __nv_bfloat16* out = g_Pbf + (size_t)gwarp * CH;
#pragma unroll
    for (int j = 0; j < 8; j++) out[lane + j * 32] = __float2bfloat16(v[j] * inv);
    if (lane == 0) {
        const float* l = L + gwarp * NCLS;
        float best = l[0]; int bc = 0;
#pragma unroll
        for (int k = 1; k < NCLS; k++) if (l[k] > best) { best = l[k]; bc = k; }
        g_clsP[gwarp] = bc;
        atomicAdd(&g_cnt[bc], 1);
    }
}

// ---------------------------------------------------------------------------
// Kernel 3: persistent-A bf16 HMMA GEMM. grid=128, 512 threads (16 warps,
// 4 warps/SMSP for latency hiding). Warp tile 32x32, warp grid 4x4.
// A resident; 16 n-tiles, 2-stage cp.async B pipeline; register bucket sums.
// ---------------------------------------------------------------------------
__global__ __launch_bounds__(512) void gemm_persist(void) {
    extern __shared__ __align__(16) char smem[];
    uint32_t sb = smem_u32(smem);
    int tid  = threadIdx.x;
    int wid  = tid >> 5;
    int lane = tid & 31;
    int m0   = blockIdx.x * GM;

    // ---- prologue: cp.async A tile + class tables + B0, B1
    const uint4* Ag = (const uint4*)(g_Xbf + (size_t)m0 * CH);
#pragma unroll
    for (int i = 0; i < 8; i++) {
        int idx = tid + i * 512;
        int row = idx >> 5, chunk = idx & 31;
        CP16(sb + OFF_A + (row * 33 + chunk) * 16, Ag + idx);
    }
    CP16(sb + OFF_CLSB + tid * 16, ((const uint4*)g_clsP) + tid);
    if (tid < 32)
        CP16(sb + OFF_CLSA + tid * 16, ((const uint4*)(g_clsV + m0)) + tid);
    {
        const uint4* Bg = (const uint4*)(g_Pbf);
#pragma unroll
        for (int i = 0; i < 8; i++) {
            int idx = tid + i * 512;
            int row = idx >> 5, chunk = idx & 31;
            CP16(sb + OFF_B0 + (row * 33 + chunk) * 16, Bg + idx);
        }
    }
    CP_COMMIT();
    {
        const uint4* Bg = (const uint4*)(g_Pbf + (size_t)GN * CH);
#pragma unroll
        for (int i = 0; i < 8; i++) {
            int idx = tid + i * 512;
            int row = idx >> 5, chunk = idx & 31;
            CP16(sb + OFF_B0 + TILE_SZ + (row * 33 + chunk) * 16, Bg + idx);
        }
    }
    CP_COMMIT();

    int wm0 = (wid >> 2) * 32;      // m quarter (4x4 warp grid)
    int wn0 = (wid & 3) * 32;       // n quarter (within tile)

    uint32_t aBase = sb + OFF_A + (uint32_t)(wm0 + (lane & 15)) * ASTRIDE + (lane >> 4) * 16;
    uint32_t bOff  = (uint32_t)(wn0 + (lane & 15)) * ASTRIDE + (lane >> 4) * 16;

    const int* sClsA = (const int*)(smem + OFF_CLSA);
    const int* sClsB = (const int*)(smem + OFF_CLSB);

    // persistent bucket accumulators (rows fixed per thread): mi=0,1
    float sAa[2], oAa[2], sBa[2], oBa[2];
#pragma unroll
    for (int mi = 0; mi < 2; mi++) { sAa[mi] = oAa[mi] = sBa[mi] = oBa[mi] = 0.0f; }

    int colBase = wn0 + (lane & 3) * 2;

    for (int t = 0; t < NT; t++) {
        if (t < NT - 1) CP_WAIT(1); else CP_WAIT(0);
        __syncthreads();

        uint32_t bBase = sb + OFF_B0 + (uint32_t)(t & 1) * TILE_SZ + bOff;

        float acc[2][4][4];
#pragma unroll
        for (int mi = 0; mi < 2; mi++)
#pragma unroll
            for (int ni = 0; ni < 4; ni++)
#pragma unroll
                for (int r = 0; r < 4; r++) acc[mi][ni][r] = 0.0f;

#pragma unroll
        for (int k0 = 0; k0 < CH; k0 += 16) {
            uint32_t a[2][4], b[4][2];
#pragma unroll
            for (int mi = 0; mi < 2; mi++)
                ldsm_x4(aBase + mi * 16 * ASTRIDE + k0 * 2,
                        a[mi][0], a[mi][1], a[mi][2], a[mi][3]);
#pragma unroll
            for (int nj = 0; nj < 2; nj++) {
                uint32_t t0, t1, t2, t3;
                ldsm_x4(bBase + nj * 16 * ASTRIDE + k0 * 2, t0, t1, t2, t3);
                b[nj * 2 + 0][0] = t0; b[nj * 2 + 0][1] = t2;
                b[nj * 2 + 1][0] = t1; b[nj * 2 + 1][1] = t3;
            }
#pragma unroll
            for (int mi = 0; mi < 2; mi++)
#pragma unroll
                for (int ni = 0; ni < 4; ni++)
                    mma_bf16(acc[mi][ni], a[mi], b[ni]);
        }

        // per-tile epilogue: exp + bucket into persistent registers
        int nGlob = t * GN;
#pragma unroll
        for (int mi = 0; mi < 2; mi++) {
            int rA = wm0 + mi * 16 + (lane >> 2);
            int cvA = sClsA[rA];
            int cvB = sClsA[rA + 8];
#pragma unroll
            for (int ni = 0; ni < 4; ni++) {
                int c0 = nGlob + colBase + ni * 8;
                int cls0 = sClsB[c0], cls1 = sClsB[c0 + 1];
                float e0 = __expf((acc[mi][ni][0] - 1.0f) * TEMP_INV);
                float e1 = __expf((acc[mi][ni][1] - 1.0f) * TEMP_INV);
                float e2 = __expf((acc[mi][ni][2] - 1.0f) * TEMP_INV);
                float e3 = __expf((acc[mi][ni][3] - 1.0f) * TEMP_INV);
                if (cls0 == cvA) sAa[mi] += e0; else oAa[mi] += e0;
                if (cls1 == cvA) sAa[mi] += e1; else oAa[mi] += e1;
                if (cls0 == cvB) sBa[mi] += e2; else oBa[mi] += e2;
                if (cls1 == cvB) sBa[mi] += e3; else oBa[mi] += e3;
            }
        }

        __syncthreads();   // protect B buffer before reissue
        if (t + 2 < NT) {
            const uint4* Bg = (const uint4*)(g_Pbf + (size_t)(t + 2) * GN * CH);
            uint32_t dst = sb + OFF_B0 + (uint32_t)(t & 1) * TILE_SZ;
#pragma unroll
            for (int i = 0; i < 8; i++) {
                int idx = tid + i * 512;
                int row = idx >> 5, chunk = idx & 31;
                CP16(dst + (row * 33 + chunk) * 16, Bg + idx);
            }
        }
        CP_COMMIT();       // uniform commit keeps group counts aligned
    }

    // ---- final combine: smem atomics, then store
    float* sS = (float*)(smem + OFF_RED);
    float* sO = sS + 128;
    if (tid < 128) { sS[tid] = 0.0f; sO[tid] = 0.0f; }
    __syncthreads();
#pragma unroll
    for (int mi = 0; mi < 2; mi++) {
        float sA = sAa[mi], oA = oAa[mi], sB = sBa[mi], oB = oBa[mi];
#pragma unroll
        for (int off = 1; off <= 2; off <<= 1) {
            sA += __shfl_xor_sync(0xffffffffu, sA, off);
            oA += __shfl_xor_sync(0xffffffffu, oA, off);
            sB += __shfl_xor_sync(0xffffffffu, sB, off);
            oB += __shfl_xor_sync(0xffffffffu, oB, off);
        }
        if ((lane & 3) == 0) {
            int rA = wm0 + mi * 16 + (lane >> 2);
            atomicAdd(&sS[rA], sA);
            atomicAdd(&sO[rA], oA);
            atomicAdd(&sS[rA + 8], sB);
            atomicAdd(&sO[rA + 8], oB);
        }
    }
    __syncthreads();
    if (tid < 128) {
        g_same[m0 + tid]  = sS[tid];
        g_other[m0 + tid] = sO[tid];
    }
}

// ---------------------------------------------------------------------------
// Kernel 4: ratios + mean (single block)
// ---------------------------------------------------------------------------
__global__ void finalize(float* __restrict__ out) {
    __shared__ float red[1024];
    int tid = threadIdx.x;
    float acc = 0.0f;
    for (int m = tid; m < VT; m += 1024) {
        int   c   = g_clsV[m];
        float cnt = (float)g_cnt[c];
        float sm  = ((float)NP - cnt) + g_same[m];
        float ot  = cnt + g_other[m];
        acc += sm / ot;
    }
    red[tid] = acc;
    __syncthreads();
    for (int s = 512; s; s >>= 1) {
        if (tid < s) red[tid] += red[tid + s];
        __syncthreads();
    }
    if (tid == 0) out[0] = red[0] / (float)VT;
}

// ---------------------------------------------------------------------------
extern "C" void kernel_launch(void* const* d_in, const int* in_sizes, int n_in,
                              void* d_out, int out_size) {
    const float* X = (const float*)d_in[0];   // (4,256,64,64)
    const float* Y = (const float*)d_in[1];   // (4,4,64,64)
    const float* P = (const float*)d_in[2];   // (2048,256)
    const float* L = (const float*)d_in[3];   // (2048,4)
    float* out = (float*)d_out;

    cudaFuncSetAttribute(gemm_persist, cudaFuncAttributeMaxDynamicSharedMemorySize, SMEM_TOTAL);

    prep_x_fused<<<dim3(HW / 32, BQ), 256>>>(X, Y);
    prep_p<<<(NP * 32) / 256, 256>>>(P, L);
    gemm_persist<<<VT / GM, 512, SMEM_TOTAL>>>();
    finalize<<<1, 1024>>>(out);
}

// round 10
// speedup vs baseline: 5.4676x; 1.0493x over previous
#include <cuda_runtime.h>
#include <cuda_bf16.h>
#include <cstdint>
#include <math.h>

// Problem constants
#define BQ   4
#define CH   256
#define HW   4096
#define VT   (BQ*HW)          // 16384 vertices
#define NP   2048             // past samples
#define NCLS 4
#define TEMP_INV 10.0f
#define EPS  1e-8f

// GEMM tiling: persistent-A. One CTA per 128-row M block, loops 16 N-tiles.
#define GM 128
#define GN 128
#define NT (NP/GN)            // 16 n-tiles

// SMEM: padded rows (264 bf16 = 528 B) for conflict-free ldmatrix
#define ASTRIDE  528
#define TILE_SZ  (GM*ASTRIDE)            // 67584
#define OFF_A    0
#define OFF_B0   TILE_SZ                 // two B stages
#define OFF_CLSB (3*TILE_SZ)             // 202752: all 2048 sample classes (8KB)
#define OFF_CLSA (OFF_CLSB + 8192)       // 128 ints
#define OFF_RED  (OFF_CLSA + 512)        // sSame[128], sOther[128]
#define SMEM_TOTAL (OFF_RED + 1024)      // 212480 (~207.5 KB)

// Scratch (allocation-free)
__device__ __align__(256) __nv_bfloat16 g_Xbf[VT*CH];
__device__ __align__(256) __nv_bfloat16 g_Pbf[NP*CH];
__device__ __align__(256) int   g_clsV[VT];
__device__ __align__(256) int   g_clsP[NP];
__device__ int   g_cnt[NCLS];
__device__ float g_sum;
__device__ unsigned g_done;

__device__ __forceinline__ uint32_t smem_u32(const void* p) {
    uint32_t a;
    asm("{ .reg .u64 t; cvta.to.shared.u64 t, %1; cvt.u32.u64 %0, t; }" : "=r"(a) : "l"(p));
    return a;
}
__device__ __forceinline__ void ldsm_x4(uint32_t addr, uint32_t& r0, uint32_t& r1,
                                        uint32_t& r2, uint32_t& r3) {
    asm volatile("ldmatrix.sync.aligned.m8n8.x4.shared.b16 {%0,%1,%2,%3}, [%4];"
                 : "=r"(r0), "=r"(r1), "=r"(r2), "=r"(r3) : "r"(addr));
}
__device__ __forceinline__ void mma_bf16(float* c, const uint32_t* a, const uint32_t* b) {
    asm volatile(
        "mma.sync.aligned.m16n8k16.row.col.f32.bf16.bf16.f32 "
        "{%0,%1,%2,%3}, {%4,%5,%6,%7}, {%8,%9}, {%0,%1,%2,%3};"
        : "+f"(c[0]), "+f"(c[1]), "+f"(c[2]), "+f"(c[3])
        : "r"(a[0]), "r"(a[1]), "r"(a[2]), "r"(a[3]), "r"(b[0]), "r"(b[1]));
}
#define CP16(dst, src) \
    asm volatile("cp.async.cg.shared.global [%0], [%1], 16;" :: "r"(dst), "l"(src))
#define CP_COMMIT() asm volatile("cp.async.commit_group;" ::: "memory")
#define CP_WAIT(n)  asm volatile("cp.async.wait_group %0;" :: "n"(n) : "memory")

// ---------------------------------------------------------------------------
// Kernel 1 (fused): single pass over X -> inverse norm, class, bf16 transpose.
// Block: 32 vertices x 256 channels, 256 threads. Grid: (HW/32, BQ).
// Also re-zeroes g_cnt / g_sum / g_done every launch (graph-replay safe).
// ---------------------------------------------------------------------------
__global__ __launch_bounds__(256) void prep_x_fused(const float* __restrict__ X,
                                                    const float* __restrict__ Y) {
    __shared__ float sx[32][257];
    __shared__ float sInv[32];
    int t  = threadIdx.x;
    int b  = blockIdx.y;
    int v0 = blockIdx.x * 32;

    if (blockIdx.x == 0 && b == 0) {
        if (t < NCLS) g_cnt[t] = 0;
        if (t == 4)  g_sum = 0.0f;
        if (t == 5)  g_done = 0u;
    }

    const float* xb = X + (size_t)b * CH * HW + v0;
#pragma unroll
    for (int i = 0; i < 32; i++) {
        int c = i * 8 + (t >> 5);
        int v = t & 31;
        sx[v][c] = xb[(size_t)c * HW + v];
    }
    __syncthreads();

    {
        int v = t >> 3, part = t & 7;
        float acc = 0.0f;
#pragma unroll
        for (int j = 0; j < 32; j++) {
            float x = sx[v][part + 8 * j];
            acc = fmaf(x, x, acc);
        }
#pragma unroll
        for (int o = 4; o; o >>= 1) acc += __shfl_xor_sync(0xffffffffu, acc, o);
        if (part == 0) {
            sInv[v] = 1.0f / fmaxf(sqrtf(acc), EPS);
            const float* yb = Y + (size_t)b * NCLS * HW + v0 + v;
            float best = yb[0]; int bc = 0;
#pragma unroll
            for (int k = 1; k < NCLS; k++) {
                float val = yb[(size_t)k * HW];
                if (val > best) { best = val; bc = k; }
            }
            g_clsV[b * HW + v0 + v] = bc;
        }
    }
    __syncthreads();

    uint32_t* out = (uint32_t*)g_Xbf + ((size_t)(b * HW + v0)) * (CH / 2);
#pragma unroll
    for (int i = 0; i < 16; i++) {
        int idx = t + i * 256;
        int v = idx >> 7, cu = idx & 127;
        float inv = sInv[v];
        __nv_bfloat162 pk = __floats2bfloat162_rn(sx[v][2 * cu] * inv,
                                                  sx[v][2 * cu + 1] * inv);
        out[(size_t)v * 128 + cu] = *(uint32_t*)&pk;
    }
}

// ---------------------------------------------------------------------------
// Kernel 2: normalize past samples -> bf16, class + counts
// ---------------------------------------------------------------------------
__global__ void prep_p(const float* __restrict__ P,
                       const float* __restrict__ L) {
    int gwarp = (blockIdx.x * blockDim.x + threadIdx.x) >> 5;
    int lane  = threadIdx.x & 31;
    if (gwarp >= NP) return;
    const float* p = P + (size_t)gwarp * CH;
    float v[8];
    float acc = 0.0f;
#pragma unroll
    for (int j = 0; j < 8; j++) {
        v[j] = p[lane + j * 32];
        acc = fmaf(v[j], v[j], acc);
    }
#pragma unroll
    for (int o = 16; o; o >>= 1) acc += __shfl_xor_sync(0xffffffffu, acc, o);
    float inv = 1.0f / fmaxf(sqrtf(acc), EPS);
    __nv_bfloat16* out = g_Pbf + (size_t)gwarp * CH;
#pragma unroll
    for (int j = 0; j < 8; j++) out[lane + j * 32] = __float2bfloat16(v[j] * inv);
    if (lane == 0) {
        const float* l = L + gwarp * NCLS;
        float best = l[0]; int bc = 0;
#pragma unroll
        for (int k = 1; k < NCLS; k++) if (l[k] > best) { best = l[k]; bc = k; }
        g_clsP[gwarp] = bc;
        atomicAdd(&g_cnt[bc], 1);
    }
}

// ---------------------------------------------------------------------------
// Kernel 3: persistent-A bf16 HMMA GEMM + fused ratio/mean finalization.
// grid=128, 512 threads (16 warps, 4/SMSP). Warp tile 32x32, warp grid 4x4.
// Last CTA to finish writes the scalar output (threadfence + counter).
// ---------------------------------------------------------------------------
__global__ __launch_bounds__(512) void gemm_persist(float* __restrict__ outp) {
    extern __shared__ __align__(16) char smem[];
    uint32_t sb = smem_u32(smem);
    int tid  = threadIdx.x;
    int wid  = tid >> 5;
    int lane = tid & 31;
    int m0   = blockIdx.x * GM;

    // ---- prologue: cp.async A tile + class tables + B0, B1
    const uint4* Ag = (const uint4*)(g_Xbf + (size_t)m0 * CH);
#pragma unroll
    for (int i = 0; i < 8; i++) {
        int idx = tid + i * 512;
        int row = idx >> 5, chunk = idx & 31;
        CP16(sb + OFF_A + (row * 33 + chunk) * 16, Ag + idx);
    }
    CP16(sb + OFF_CLSB + tid * 16, ((const uint4*)g_clsP) + tid);
    if (tid < 32)
        CP16(sb + OFF_CLSA + tid * 16, ((const uint4*)(g_clsV + m0)) + tid);
    {
        const uint4* Bg = (const uint4*)(g_Pbf);
#pragma unroll
        for (int i = 0; i < 8; i++) {
            int idx = tid + i * 512;
            int row = idx >> 5, chunk = idx & 31;
            CP16(sb + OFF_B0 + (row * 33 + chunk) * 16, Bg + idx);
        }
    }
    CP_COMMIT();
    {
        const uint4* Bg = (const uint4*)(g_Pbf + (size_t)GN * CH);
#pragma unroll
        for (int i = 0; i < 8; i++) {
            int idx = tid + i * 512;
            int row = idx >> 5, chunk = idx & 31;
            CP16(sb + OFF_B0 + TILE_SZ + (row * 33 + chunk) * 16, Bg + idx);
        }
    }
    CP_COMMIT();

    int wm0 = (wid >> 2) * 32;      // m quarter (4x4 warp grid)
    int wn0 = (wid & 3) * 32;       // n quarter (within tile)

    uint32_t aBase = sb + OFF_A + (uint32_t)(wm0 + (lane & 15)) * ASTRIDE + (lane >> 4) * 16;
    uint32_t bOff  = (uint32_t)(wn0 + (lane & 15)) * ASTRIDE + (lane >> 4) * 16;

    const int* sClsA = (const int*)(smem + OFF_CLSA);
    const int* sClsB = (const int*)(smem + OFF_CLSB);

    float sAa[2], oAa[2], sBa[2], oBa[2];
#pragma unroll
    for (int mi = 0; mi < 2; mi++) { sAa[mi] = oAa[mi] = sBa[mi] = oBa[mi] = 0.0f; }

    int colBase = wn0 + (lane & 3) * 2;

    for (int t = 0; t < NT; t++) {
        if (t < NT - 1) CP_WAIT(1); else CP_WAIT(0);
        __syncthreads();

        uint32_t bBase = sb + OFF_B0 + (uint32_t)(t & 1) * TILE_SZ + bOff;

        float acc[2][4][4];
#pragma unroll
        for (int mi = 0; mi < 2; mi++)
#pragma unroll
            for (int ni = 0; ni < 4; ni++)
#pragma unroll
                for (int r = 0; r < 4; r++) acc[mi][ni][r] = 0.0f;

#pragma unroll
        for (int k0 = 0; k0 < CH; k0 += 16) {
            uint32_t a[2][4], b[4][2];
#pragma unroll
            for (int mi = 0; mi < 2; mi++)
                ldsm_x4(aBase + mi * 16 * ASTRIDE + k0 * 2,
                        a[mi][0], a[mi][1], a[mi][2], a[mi][3]);
#pragma unroll
            for (int nj = 0; nj < 2; nj++) {
                uint32_t t0, t1, t2, t3;
                ldsm_x4(bBase + nj * 16 * ASTRIDE + k0 * 2, t0, t1, t2, t3);
                b[nj * 2 + 0][0] = t0; b[nj * 2 + 0][1] = t2;
                b[nj * 2 + 1][0] = t1; b[nj * 2 + 1][1] = t3;
            }
#pragma unroll
            for (int mi = 0; mi < 2; mi++)
#pragma unroll
                for (int ni = 0; ni < 4; ni++)
                    mma_bf16(acc[mi][ni], a[mi], b[ni]);
        }

        int nGlob = t * GN;
#pragma unroll
        for (int mi = 0; mi < 2; mi++) {
            int rA = wm0 + mi * 16 + (lane >> 2);
            int cvA = sClsA[rA];
            int cvB = sClsA[rA + 8];
#pragma unroll
            for (int ni = 0; ni < 4; ni++) {
                int c0 = nGlob + colBase + ni * 8;
                int cls0 = sClsB[c0], cls1 = sClsB[c0 + 1];
                float e0 = __expf((acc[mi][ni][0] - 1.0f) * TEMP_INV);
                float e1 = __expf((acc[mi][ni][1] - 1.0f) * TEMP_INV);
                float e2 = __expf((acc[mi][ni][2] - 1.0f) * TEMP_INV);
                float e3 = __expf((acc[mi][ni][3] - 1.0f) * TEMP_INV);
                if (cls0 == cvA) sAa[mi] += e0; else oAa[mi] += e0;
                if (cls1 == cvA) sAa[mi] += e1; else oAa[mi] += e1;
                if (cls0 == cvB) sBa[mi] += e2; else oBa[mi] += e2;
                if (cls1 == cvB) sBa[mi] += e3; else oBa[mi] += e3;
            }
        }

        __syncthreads();   // protect B buffer before reissue
        if (t + 2 < NT) {
            const uint4* Bg = (const uint4*)(g_Pbf + (size_t)(t + 2) * GN * CH);
            uint32_t dst = sb + OFF_B0 + (uint32_t)(t & 1) * TILE_SZ;
#pragma unroll
            for (int i = 0; i < 8; i++) {
                int idx = tid + i * 512;
                int row = idx >> 5, chunk = idx & 31;
                CP16(dst + (row * 33 + chunk) * 16, Bg + idx);
            }
        }
        CP_COMMIT();
    }

    // ---- fused finalize: combine buckets, compute per-row ratio, CTA-sum,
    // atomicAdd partial; last CTA writes the mean.
    float* sS = (float*)(smem + OFF_RED);
    float* sO = sS + 128;
    if (tid < 128) { sS[tid] = 0.0f; sO[tid] = 0.0f; }
    __syncthreads();
#pragma unroll
    for (int mi = 0; mi < 2; mi++) {
        float sA = sAa[mi], oA = oAa[mi], sB = sBa[mi], oB = oBa[mi];
#pragma unroll
        for (int off = 1; off <= 2; off <<= 1) {
            sA += __shfl_xor_sync(0xffffffffu, sA, off);
            oA += __shfl_xor_sync(0xffffffffu, oA, off);
            sB += __shfl_xor_sync(0xffffffffu, sB, off);
            oB += __shfl_xor_sync(0xffffffffu, oB, off);
        }
        if ((lane & 3) == 0) {
            int rA = wm0 + mi * 16 + (lane >> 2);
            atomicAdd(&sS[rA], sA);
            atomicAdd(&sO[rA], oA);
            atomicAdd(&sS[rA + 8], sB);
            atomicAdd(&sO[rA + 8], oB);
        }
    }
    __syncthreads();

    // per-row ratio (tid<128), then 4-warp reduce via shuffles + smem
    __shared__ float wsum[4];
    if (tid < 128) {
        float cnt = (float)g_cnt[sClsA[tid]];
        float r = (((float)NP - cnt) + sS[tid]) / (cnt + sO[tid]);
#pragma unroll
        for (int off = 16; off; off >>= 1) r += __shfl_xor_sync(0xffffffffu, r, off);
        if (lane == 0) wsum[wid] = r;
    }
    __syncthreads();
    if (tid == 0) {
        float part = wsum[0] + wsum[1] + wsum[2] + wsum[3];
        atomicAdd(&g_sum, part);
        __threadfence();
        unsigned d = atomicAdd(&g_done, 1u);
        if (d == (unsigned)(gridDim.x - 1)) {
            outp[0] = g_sum / (float)VT;
        }
    }
}

// ---------------------------------------------------------------------------
extern "C" void kernel_launch(void* const* d_in, const int* in_sizes, int n_in,
                              void* d_out, int out_size) {
    const float* X = (const float*)d_in[0];   // (4,256,64,64)
    const float* Y = (const float*)d_in[1];   // (4,4,64,64)
    const float* P = (const float*)d_in[2];   // (2048,256)
    const float* L = (const float*)d_in[3];   // (2048,4)
    float* out = (float*)d_out;

    cudaFuncSetAttribute(gemm_persist, cudaFuncAttributeMaxDynamicSharedMemorySize, SMEM_TOTAL);

    prep_x_fused<<<dim3(HW / 32, BQ), 256>>>(X, Y);
    prep_p<<<(NP * 32) / 256, 256>>>(P, L);
    gemm_persist<<<VT / GM, 512, SMEM_TOTAL>>>(out);
}